// round 14
// baseline (speedup 1.0000x reference)
#include <cuda_runtime.h>
#include <cuda_fp16.h>
#include <cstdint>

// =====================================================================
// RBF-kernel causal attention, fp16 HMMA + per-row power-of-2 P scaling.
// Round 14: BN 64 -> 96 (per-tile fixed costs amortized over 1.5x work),
// 2 CTAs/SM (smem ~103KB/CTA). Causal mask only on straddling tiles.
//   l2_ij = log2e*(2s*(q.k) - s||q||^2 - s||k||^2); p = 2^(l2 - b_row);
//   b_row = running max(l2) - 14; O at scale 2^-b, rescaled on growth.
// QK^T and PV both 1-term fp16 (error calibrated rounds 7-13: ~5.4e-4).
// 2-stage cp.async; intra-tile QK/logit interleave; prepass K/V only.
// =====================================================================

namespace {
constexpr int NSEQ = 2048;
constexpr int DDIM = 128;
constexpr int BM   = 64;
constexpr int BN   = 96;
constexpr int NBH  = 32;                      // B*H
constexpr int NROWS = NBH * NSEQ;             // 65536
constexpr int PADR  = 96;                     // row padding (last-bh overread)
constexpr size_t TOTE = (size_t)(NROWS + PADR) * DDIM;
constexpr float SM_SCALE = 0.08838834764831845f;   // 1/sqrt(128)
constexpr float LOG2E    = 1.4426950408889634f;
constexpr float C2       = 2.0f * SM_SCALE * LOG2E;

constexpr int PITCH = 272;   // smem tile row pitch (bytes): 256 data + 16 pad
constexpr uint32_t OFF_V       = (uint32_t)BN * PITCH;      // V inside stage
constexpr uint32_t STAGE_BYTES = 2u * BN * PITCH;           // K + V = 52224
constexpr uint32_t OFF_KSQ     = 2 * STAGE_BYTES;           // 2 x 384B
constexpr uint32_t SMEM_BYTES  = OFF_KSQ + 768 + 128;       // 105344 per CTA
}

// ---- persistent scratch (alloc-free workaround; zero-init pads) ----
__device__ __half g_kh[TOTE];
__device__ __half g_vh[TOTE];
__device__ float  g_ksq[NROWS + PADR];   // log2e * s * ||k||^2

__device__ __forceinline__ uint32_t smem_u32(const void* p) {
    uint32_t a;
    asm("{ .reg .u64 t; cvta.to.shared.u64 t, %1; cvt.u32.u64 %0, t; }"
        : "=r"(a) : "l"(p));
    return a;
}
__device__ __forceinline__ void cp16(uint32_t smem_dst, const void* gsrc) {
    asm volatile("cp.async.cg.shared.global [%0], [%1], 16;"
                 :: "r"(smem_dst), "l"(gsrc));
}
__device__ __forceinline__ void cp_commit() {
    asm volatile("cp.async.commit_group;" ::: "memory");
}
__device__ __forceinline__ void cp_wait1() {
    asm volatile("cp.async.wait_group 1;" ::: "memory");
}
__device__ __forceinline__ void ldsm_x4(uint32_t* r, uint32_t addr) {
    asm volatile("ldmatrix.sync.aligned.m8n8.x4.shared.b16 {%0,%1,%2,%3}, [%4];"
                 : "=r"(r[0]), "=r"(r[1]), "=r"(r[2]), "=r"(r[3]) : "r"(addr));
}
__device__ __forceinline__ void ldsm_x4_t(uint32_t* r, uint32_t addr) {
    asm volatile("ldmatrix.sync.aligned.m8n8.x4.trans.shared.b16 {%0,%1,%2,%3}, [%4];"
                 : "=r"(r[0]), "=r"(r[1]), "=r"(r[2]), "=r"(r[3]) : "r"(addr));
}
__device__ __forceinline__ void mma_fp16(float* d, const uint32_t* a,
                                         uint32_t b0, uint32_t b1) {
    asm volatile(
        "mma.sync.aligned.m16n8k16.row.col.f32.f16.f16.f32 "
        "{%0,%1,%2,%3}, {%4,%5,%6,%7}, {%8,%9}, {%0,%1,%2,%3};"
        : "+f"(d[0]), "+f"(d[1]), "+f"(d[2]), "+f"(d[3])
        : "r"(a[0]), "r"(a[1]), "r"(a[2]), "r"(a[3]), "r"(b0), "r"(b1));
}
__device__ __forceinline__ float ex2(float x) {
    float y;
    asm("ex2.approx.ftz.f32 %0, %1;" : "=f"(y) : "f"(x));
    return y;
}

// =========================== pre-pass (K, V only) ===========================
__global__ __launch_bounds__(256)
void prepass(const float* __restrict__ gk,
             const float* __restrict__ gv) {
    const int warp = threadIdx.x >> 5;
    const int lane = threadIdx.x & 31;
    const int row  = blockIdx.x * 8 + warp;
    const size_t e = (size_t)row * DDIM + lane * 4;

    float4 kx = *(const float4*)(gk + e);
    {
        __half2 a = __floats2half2_rn(kx.x, kx.y);
        __half2 b = __floats2half2_rn(kx.z, kx.w);
        *(uint2*)&g_kh[e] = make_uint2(*(uint32_t*)&a, *(uint32_t*)&b);
    }
    float s2 = kx.x*kx.x + kx.y*kx.y + kx.z*kx.z + kx.w*kx.w;
    #pragma unroll
    for (int o = 16; o; o >>= 1) s2 += __shfl_xor_sync(0xffffffffu, s2, o);
    if (lane == 0) g_ksq[row] = (SM_SCALE * LOG2E) * s2;

    float4 vx = *(const float4*)(gv + e);
    {
        __half2 a = __floats2half2_rn(vx.x, vx.y);
        __half2 b = __floats2half2_rn(vx.z, vx.w);
        *(uint2*)&g_vh[e] = make_uint2(*(uint32_t*)&a, *(uint32_t*)&b);
    }
}

// =========================== main kernel ===========================
__global__ __launch_bounds__(128, 2)
void rbf_attn_hmma(const float* __restrict__ gq, float* __restrict__ gout) {
    extern __shared__ char smc[];
    const uint32_t smb = smem_u32(smc);
    const int tid  = threadIdx.x;
    const int warp = tid >> 5;        // 0..3
    const int lane = tid & 31;
    const int g    = lane >> 2;
    const int tig  = lane & 3;
    const int iq   = (int)gridDim.x - 1 - (int)blockIdx.x;   // big tiles first
    const int bh   = blockIdx.y;

    const size_t rowbase = (size_t)bh * NSEQ;
    const int lastrow = iq * BM + 63;
    const int njt = lastrow / BN + 1;                 // tiles covering cols<=lastrow
    // first tile needing causal mask: 96*jt + 95 > 64*iq
    const int jt0 = (96 * 0 + 95 > 64 * iq) ? 0 : ((64 * iq - 95) / 96 + 1);

    // ---- stage loader: K + V + ksq of tile jt, one commit group ----
    auto issue_KV = [&](int jt) {
        if (jt < njt) {
            const uint32_t stg = (uint32_t)(jt & 1) * STAGE_BYTES;
            const size_t eb = (rowbase + (size_t)jt * BN) * DDIM;
            #pragma unroll
            for (int i = 0; i < 12; i++) {
                int c = i * 128 + tid;           // 0..1535
                int r = c >> 4, col = c & 15;
                uint32_t d = (uint32_t)(r * PITCH + col * 16);
                const size_t gsrc = eb + r * DDIM + col * 8;
                cp16(smb + stg + d,         g_kh + gsrc);
                cp16(smb + stg + OFF_V + d, g_vh + gsrc);
            }
            if (tid < 24)
                cp16(smb + OFF_KSQ + (uint32_t)((jt & 1) * 384 + tid * 16),
                     g_ksq + rowbase + jt * BN + tid * 4);
        }
        cp_commit();
    };

    issue_KV(0);
    issue_KV(1);

    // ---- prologue: Q fp32 -> fp16 fragments + log2-scaled row norms ----
    const int rowA = warp * 16 + g;           // 0..63
    const int rA   = iq * BM + rowA;          // row within head
    const int rB   = rA + 8;
    const float* qA = gq + (rowbase + rA) * (size_t)DDIM;
    const float* qB = qA + 8 * DDIM;
    uint32_t Qf[8][4];
    float q2a = 0.f, q2b = 0.f;
    #pragma unroll
    for (int kb8 = 0; kb8 < 8; kb8++) {
        int c0 = kb8 * 16 + 2 * tig;
        float2 a0 = *(const float2*)(qA + c0);
        float2 a1 = *(const float2*)(qA + c0 + 8);
        float2 b0 = *(const float2*)(qB + c0);
        float2 b1 = *(const float2*)(qB + c0 + 8);
        q2a += a0.x*a0.x + a0.y*a0.y + a1.x*a1.x + a1.y*a1.y;
        q2b += b0.x*b0.x + b0.y*b0.y + b1.x*b1.x + b1.y*b1.y;
        __half2 ha0 = __floats2half2_rn(a0.x, a0.y);
        __half2 hb0 = __floats2half2_rn(b0.x, b0.y);
        __half2 ha1 = __floats2half2_rn(a1.x, a1.y);
        __half2 hb1 = __floats2half2_rn(b1.x, b1.y);
        Qf[kb8][0] = *(uint32_t*)&ha0;
        Qf[kb8][1] = *(uint32_t*)&hb0;
        Qf[kb8][2] = *(uint32_t*)&ha1;
        Qf[kb8][3] = *(uint32_t*)&hb1;
    }
    q2a += __shfl_xor_sync(0xffffffffu, q2a, 1);
    q2a += __shfl_xor_sync(0xffffffffu, q2a, 2);
    q2b += __shfl_xor_sync(0xffffffffu, q2b, 1);
    q2b += __shfl_xor_sync(0xffffffffu, q2b, 2);
    q2a *= SM_SCALE * LOG2E;
    q2b *= SM_SCALE * LOG2E;

    float O[16][4];
    #pragma unroll
    for (int i = 0; i < 16; i++)
        #pragma unroll
        for (int j = 0; j < 4; j++) O[i][j] = 0.f;
    float b_a = -3e30f, b_b = -3e30f;   // running log2-bias per row half

    const uint32_t k_laneoff = (uint32_t)(((lane & 7) + ((lane & 16) >> 1)) * PITCH
                                          + (lane & 8) * 2);
    const uint32_t v_laneoff = (uint32_t)(((lane & 7) + (lane & 8)) * PITCH
                                          + (lane & 16));

    float S[12][4];
    float ksr_e[12], ksr_o[12];
    float mxa, mxb;

    // qk chunk ntp (0..5): 8 ldsm + 16 MMAs finishing S[2ntp], S[2ntp+1]
    auto qk_chunk = [&](uint32_t kbase, int ntp) {
        S[2*ntp][0] = 0.f; S[2*ntp][1] = 0.f; S[2*ntp][2] = 0.f; S[2*ntp][3] = 0.f;
        S[2*ntp+1][0] = 0.f; S[2*ntp+1][1] = 0.f; S[2*ntp+1][2] = 0.f; S[2*ntp+1][3] = 0.f;
        #pragma unroll
        for (int kb8 = 0; kb8 < 8; kb8++) {
            uint32_t bp[4];
            ldsm_x4(bp, kbase + (uint32_t)(ntp * 16 * PITCH + kb8 * 32));
            mma_fp16(S[2*ntp],   Qf[kb8], bp[0], bp[1]);
            mma_fp16(S[2*ntp+1], Qf[kb8], bp[2], bp[3]);
        }
    };
    // logit chunk ntp: transform S -> l2 (+optional mask), accumulate max
    auto lg_chunk = [&](int ntp, bool diag, int jt) {
        #pragma unroll
        for (int h = 0; h < 2; h++) {
            int nt = 2 * ntp + h;
            float ks0 = h ? ksr_o[2*ntp]     : ksr_e[2*ntp];
            float ks1 = h ? ksr_o[2*ntp + 1] : ksr_e[2*ntp + 1];
            float a0 = fmaf(C2, S[nt][0], -(q2a + ks0));
            float a1 = fmaf(C2, S[nt][1], -(q2a + ks1));
            float c0 = fmaf(C2, S[nt][2], -(q2b + ks0));
            float c1 = fmaf(C2, S[nt][3], -(q2b + ks1));
            if (diag) {
                int cg = jt * BN + nt * 8 + 2 * tig;
                if (cg     > rA) a0 = -3e30f;
                if (cg + 1 > rA) a1 = -3e30f;
                if (cg     > rB) c0 = -3e30f;
                if (cg + 1 > rB) c1 = -3e30f;
            }
            S[nt][0] = a0; S[nt][1] = a1; S[nt][2] = c0; S[nt][3] = c1;
            mxa = fmaxf(mxa, fmaxf(a0, a1));
            mxb = fmaxf(mxb, fmaxf(c0, c1));
        }
    };

    auto tile_body = [&](int jt, bool diag) {
        const uint32_t stg = (uint32_t)(jt & 1) * STAGE_BYTES;
        cp_wait1();
        __syncthreads();

        // ksq -> registers (independent of MMAs; issue early)
        {
            const float* sksq = (const float*)(smc + OFF_KSQ + (jt & 1) * 384);
            #pragma unroll
            for (int q4 = 0; q4 < 6; q4++) {
                float2 ke = *(const float2*)(sksq + q4 * 16 + 2 * tig);
                float2 ko = *(const float2*)(sksq + q4 * 16 + 8 + 2 * tig);
                ksr_e[2*q4] = ke.x; ksr_e[2*q4 + 1] = ke.y;
                ksr_o[2*q4] = ko.x; ksr_o[2*q4 + 1] = ko.y;
            }
        }

        mxa = -3e30f; mxb = -3e30f;
        const uint32_t kbase = smb + stg + k_laneoff;
        // pipeline: logit ALU of chunk c overlaps MMA drain of later chunks
        qk_chunk(kbase, 0);
        qk_chunk(kbase, 1);
        qk_chunk(kbase, 2);
        lg_chunk(0, diag, jt);
        qk_chunk(kbase, 3);
        lg_chunk(1, diag, jt);
        qk_chunk(kbase, 4);
        lg_chunk(2, diag, jt);
        qk_chunk(kbase, 5);
        lg_chunk(3, diag, jt);
        lg_chunk(4, diag, jt);
        lg_chunk(5, diag, jt);

        mxa = fmaxf(mxa, __shfl_xor_sync(0xffffffffu, mxa, 1));
        mxa = fmaxf(mxa, __shfl_xor_sync(0xffffffffu, mxa, 2));
        mxb = fmaxf(mxb, __shfl_xor_sync(0xffffffffu, mxb, 1));
        mxb = fmaxf(mxb, __shfl_xor_sync(0xffffffffu, mxb, 2));

        float bna = fmaxf(b_a, mxa - 14.f);
        if (bna > b_a) {
            float f = ex2(b_a - bna);
            #pragma unroll
            for (int dt = 0; dt < 16; dt++) { O[dt][0] *= f; O[dt][1] *= f; }
            b_a = bna;
        }
        float bnb = fmaxf(b_b, mxb - 14.f);
        if (bnb > b_b) {
            float f = ex2(b_b - bnb);
            #pragma unroll
            for (int dt = 0; dt < 16; dt++) { O[dt][2] *= f; O[dt][3] *= f; }
            b_b = bnb;
        }

        // fused exp + PV per 16-col chunk (MUFU overlaps tensor)
        const uint32_t vbase = smb + stg + OFF_V + v_laneoff;
        #pragma unroll
        for (int kj = 0; kj < 6; kj++) {
            uint32_t Pf[4];
            #pragma unroll
            for (int h = 0; h < 2; h++) {
                int nt = kj * 2 + h;
                float p0 = ex2(S[nt][0] - b_a);
                float p1 = ex2(S[nt][1] - b_a);
                float p2 = ex2(S[nt][2] - b_b);
                float p3 = ex2(S[nt][3] - b_b);
                __half2 ha = __floats2half2_rn(p0, p1);
                __half2 hb = __floats2half2_rn(p2, p3);
                Pf[h * 2]     = *(uint32_t*)&ha;
                Pf[h * 2 + 1] = *(uint32_t*)&hb;
            }
            #pragma unroll
            for (int dtp = 0; dtp < 8; dtp++) {
                uint32_t vp[4];
                ldsm_x4_t(vp, vbase + (uint32_t)(kj * 16 * PITCH + dtp * 32));
                mma_fp16(O[2*dtp],   Pf, vp[0], vp[1]);
                mma_fp16(O[2*dtp+1], Pf, vp[2], vp[3]);
            }
        }

        __syncthreads();
        issue_KV(jt + 2);
    };

    for (int jt = 0; jt < jt0; jt++) tile_body(jt, false);
    for (int jt = jt0; jt < njt; jt++) tile_body(jt, true);

    // ---- epilogue: descale (O_true = O * 2^b) and store ----
    const float fa = ex2(b_a);
    const float fb = ex2(b_b);
    float* ob = gout + (size_t)bh * NSEQ * DDIM;
    float* oA = ob + (size_t)rA * DDIM;
    float* oB = ob + (size_t)rB * DDIM;
    #pragma unroll
    for (int dt = 0; dt < 16; dt++) {
        int c = dt * 8 + 2 * tig;
        *(float2*)(oA + c) = make_float2(O[dt][0] * fa, O[dt][1] * fa);
        *(float2*)(oB + c) = make_float2(O[dt][2] * fb, O[dt][3] * fb);
    }
}

extern "C" void kernel_launch(void* const* d_in, const int* in_sizes, int n_in,
                              void* d_out, int out_size) {
    const float* q = (const float*)d_in[0];
    const float* k = (const float*)d_in[1];
    const float* v = (const float*)d_in[2];
    float* out = (float*)d_out;

    prepass<<<NROWS / 8, 256>>>(k, v);

    cudaFuncSetAttribute(rbf_attn_hmma,
                         cudaFuncAttributeMaxDynamicSharedMemorySize, SMEM_BYTES);
    dim3 grid(NSEQ / BM, NBH);   // 32 q-tiles x 32 (b,h)
    rbf_attn_hmma<<<grid, 128, SMEM_BYTES>>>(q, out);
}

// round 15
// speedup vs baseline: 1.0277x; 1.0277x over previous
#include <cuda_runtime.h>
#include <cuda_fp16.h>
#include <cstdint>

// =====================================================================
// RBF-kernel causal attention, fp16 HMMA + per-row power-of-2 P scaling.
// Round 15: R13 base (BN=64, 3 CTAs/SM, 2-stage cp.async, diag-split,
// QK/logit interleave) with QK issued in CHUNK PAIRS: 4 independent
// accumulator chains in flight (R13's single-chunk order had only 2,
// serializing on the HMMA accumulator RAW ~30cyc latency).
//   l2_ij = log2e*(2s*(q.k) - s||q||^2 - s||k||^2); p = 2^(l2 - b_row);
//   b_row = running max(l2) - 14; O at scale 2^-b, rescaled on growth.
// QK^T and PV both 1-term fp16 (error calibrated rounds 7-13: ~5.4e-4).
// =====================================================================

namespace {
constexpr int NSEQ = 2048;
constexpr int DDIM = 128;
constexpr int BM   = 64;
constexpr int BN   = 64;
constexpr int NBH  = 32;                      // B*H
constexpr int NROWS = NBH * NSEQ;             // 65536
constexpr size_t TOTE = (size_t)NROWS * DDIM; // 8388608
constexpr float SM_SCALE = 0.08838834764831845f;   // 1/sqrt(128)
constexpr float LOG2E    = 1.4426950408889634f;
constexpr float C2       = 2.0f * SM_SCALE * LOG2E;

constexpr int PITCH = 272;   // smem tile row pitch (bytes): 256 data + 16 pad
constexpr uint32_t OFF_V       = 64 * PITCH;            // V offset inside stage
constexpr uint32_t STAGE_BYTES = 2u * 64 * PITCH;       // K + V = 34816
constexpr uint32_t OFF_KSQ     = 2 * STAGE_BYTES;       // 2 x 256B
constexpr uint32_t SMEM_BYTES  = OFF_KSQ + 512 + 128;   // 70272 per CTA
}

// ---- persistent scratch (alloc-free workaround) ----
__device__ __half g_kh[TOTE];
__device__ __half g_vh[TOTE];
__device__ float  g_ksq[NROWS];   // log2e * s * ||k||^2

__device__ __forceinline__ uint32_t smem_u32(const void* p) {
    uint32_t a;
    asm("{ .reg .u64 t; cvta.to.shared.u64 t, %1; cvt.u32.u64 %0, t; }"
        : "=r"(a) : "l"(p));
    return a;
}
__device__ __forceinline__ void cp16(uint32_t smem_dst, const void* gsrc) {
    asm volatile("cp.async.cg.shared.global [%0], [%1], 16;"
                 :: "r"(smem_dst), "l"(gsrc));
}
__device__ __forceinline__ void cp_commit() {
    asm volatile("cp.async.commit_group;" ::: "memory");
}
__device__ __forceinline__ void cp_wait1() {
    asm volatile("cp.async.wait_group 1;" ::: "memory");
}
__device__ __forceinline__ void ldsm_x4(uint32_t* r, uint32_t addr) {
    asm volatile("ldmatrix.sync.aligned.m8n8.x4.shared.b16 {%0,%1,%2,%3}, [%4];"
                 : "=r"(r[0]), "=r"(r[1]), "=r"(r[2]), "=r"(r[3]) : "r"(addr));
}
__device__ __forceinline__ void ldsm_x4_t(uint32_t* r, uint32_t addr) {
    asm volatile("ldmatrix.sync.aligned.m8n8.x4.trans.shared.b16 {%0,%1,%2,%3}, [%4];"
                 : "=r"(r[0]), "=r"(r[1]), "=r"(r[2]), "=r"(r[3]) : "r"(addr));
}
__device__ __forceinline__ void mma_fp16(float* d, const uint32_t* a,
                                         uint32_t b0, uint32_t b1) {
    asm volatile(
        "mma.sync.aligned.m16n8k16.row.col.f32.f16.f16.f32 "
        "{%0,%1,%2,%3}, {%4,%5,%6,%7}, {%8,%9}, {%0,%1,%2,%3};"
        : "+f"(d[0]), "+f"(d[1]), "+f"(d[2]), "+f"(d[3])
        : "r"(a[0]), "r"(a[1]), "r"(a[2]), "r"(a[3]), "r"(b0), "r"(b1));
}
__device__ __forceinline__ float ex2(float x) {
    float y;
    asm("ex2.approx.ftz.f32 %0, %1;" : "=f"(y) : "f"(x));
    return y;
}

// =========================== pre-pass (K, V only) ===========================
__global__ __launch_bounds__(256)
void prepass(const float* __restrict__ gk,
             const float* __restrict__ gv) {
    const int warp = threadIdx.x >> 5;
    const int lane = threadIdx.x & 31;
    const int row  = blockIdx.x * 8 + warp;
    const size_t e = (size_t)row * DDIM + lane * 4;

    float4 kx = *(const float4*)(gk + e);
    {
        __half2 a = __floats2half2_rn(kx.x, kx.y);
        __half2 b = __floats2half2_rn(kx.z, kx.w);
        *(uint2*)&g_kh[e] = make_uint2(*(uint32_t*)&a, *(uint32_t*)&b);
    }
    float s2 = kx.x*kx.x + kx.y*kx.y + kx.z*kx.z + kx.w*kx.w;
    #pragma unroll
    for (int o = 16; o; o >>= 1) s2 += __shfl_xor_sync(0xffffffffu, s2, o);
    if (lane == 0) g_ksq[row] = (SM_SCALE * LOG2E) * s2;

    float4 vx = *(const float4*)(gv + e);
    {
        __half2 a = __floats2half2_rn(vx.x, vx.y);
        __half2 b = __floats2half2_rn(vx.z, vx.w);
        *(uint2*)&g_vh[e] = make_uint2(*(uint32_t*)&a, *(uint32_t*)&b);
    }
}

// =========================== main kernel ===========================
__global__ __launch_bounds__(128, 3)
void rbf_attn_hmma(const float* __restrict__ gq, float* __restrict__ gout) {
    extern __shared__ char smc[];
    const uint32_t smb = smem_u32(smc);
    const int tid  = threadIdx.x;
    const int warp = tid >> 5;        // 0..3
    const int lane = tid & 31;
    const int g    = lane >> 2;
    const int tig  = lane & 3;
    const int iq   = (int)gridDim.x - 1 - (int)blockIdx.x;   // big tiles first
    const int bh   = blockIdx.y;

    const size_t rowbase = (size_t)bh * NSEQ;
    const int njt = iq + 1;

    // ---- stage loader: K + V + ksq of tile jt, one commit group ----
    auto issue_KV = [&](int jt) {
        if (jt < njt) {
            const uint32_t stg = (uint32_t)(jt & 1) * STAGE_BYTES;
            const size_t eb = (rowbase + (size_t)jt * BN) * DDIM;
            #pragma unroll
            for (int i = 0; i < 8; i++) {
                int c = i * 128 + tid;           // 0..1023
                int r = c >> 4, col = c & 15;
                uint32_t d = (uint32_t)(r * PITCH + col * 16);
                const size_t gsrc = eb + r * DDIM + col * 8;
                cp16(smb + stg + d,         g_kh + gsrc);
                cp16(smb + stg + OFF_V + d, g_vh + gsrc);
            }
            if (tid < 16)
                cp16(smb + OFF_KSQ + (uint32_t)((jt & 1) * 256 + tid * 16),
                     g_ksq + rowbase + jt * BN + tid * 4);
        }
        cp_commit();
    };

    issue_KV(0);
    issue_KV(1);

    // ---- prologue: Q fp32 -> fp16 fragments + log2-scaled row norms ----
    const int rowA = warp * 16 + g;           // 0..63
    const int rA   = iq * BM + rowA;          // row within head
    const int rB   = rA + 8;
    const float* qA = gq + (rowbase + rA) * (size_t)DDIM;
    const float* qB = qA + 8 * DDIM;
    uint32_t Qf[8][4];
    float q2a = 0.f, q2b = 0.f;
    #pragma unroll
    for (int kb8 = 0; kb8 < 8; kb8++) {
        int c0 = kb8 * 16 + 2 * tig;
        float2 a0 = *(const float2*)(qA + c0);
        float2 a1 = *(const float2*)(qA + c0 + 8);
        float2 b0 = *(const float2*)(qB + c0);
        float2 b1 = *(const float2*)(qB + c0 + 8);
        q2a += a0.x*a0.x + a0.y*a0.y + a1.x*a1.x + a1.y*a1.y;
        q2b += b0.x*b0.x + b0.y*b0.y + b1.x*b1.x + b1.y*b1.y;
        __half2 ha0 = __floats2half2_rn(a0.x, a0.y);
        __half2 hb0 = __floats2half2_rn(b0.x, b0.y);
        __half2 ha1 = __floats2half2_rn(a1.x, a1.y);
        __half2 hb1 = __floats2half2_rn(b1.x, b1.y);
        Qf[kb8][0] = *(uint32_t*)&ha0;
        Qf[kb8][1] = *(uint32_t*)&hb0;
        Qf[kb8][2] = *(uint32_t*)&ha1;
        Qf[kb8][3] = *(uint32_t*)&hb1;
    }
    q2a += __shfl_xor_sync(0xffffffffu, q2a, 1);
    q2a += __shfl_xor_sync(0xffffffffu, q2a, 2);
    q2b += __shfl_xor_sync(0xffffffffu, q2b, 1);
    q2b += __shfl_xor_sync(0xffffffffu, q2b, 2);
    q2a *= SM_SCALE * LOG2E;
    q2b *= SM_SCALE * LOG2E;

    float O[16][4];
    #pragma unroll
    for (int i = 0; i < 16; i++)
        #pragma unroll
        for (int j = 0; j < 4; j++) O[i][j] = 0.f;
    float b_a = -3e30f, b_b = -3e30f;   // running log2-bias per row half

    const uint32_t k_laneoff = (uint32_t)(((lane & 7) + ((lane & 16) >> 1)) * PITCH
                                          + (lane & 8) * 2);
    const uint32_t v_laneoff = (uint32_t)(((lane & 7) + (lane & 8)) * PITCH
                                          + (lane & 16));

    float S[8][4];
    float ksr_e[8], ksr_o[8];
    float mxa, mxb;

    // qk pair (ntp0, ntp0+1): 4 independent accumulator chains in flight
    auto qk_pair = [&](uint32_t kbase, int ntp0) {
        const int ntp1 = ntp0 + 1;
        #pragma unroll
        for (int h = 0; h < 2; h++) {
            S[2*ntp0+h][0] = 0.f; S[2*ntp0+h][1] = 0.f;
            S[2*ntp0+h][2] = 0.f; S[2*ntp0+h][3] = 0.f;
            S[2*ntp1+h][0] = 0.f; S[2*ntp1+h][1] = 0.f;
            S[2*ntp1+h][2] = 0.f; S[2*ntp1+h][3] = 0.f;
        }
        #pragma unroll
        for (int kb8 = 0; kb8 < 8; kb8++) {
            uint32_t bp0[4], bp1[4];
            ldsm_x4(bp0, kbase + (uint32_t)(ntp0 * 16 * PITCH + kb8 * 32));
            ldsm_x4(bp1, kbase + (uint32_t)(ntp1 * 16 * PITCH + kb8 * 32));
            mma_fp16(S[2*ntp0],   Qf[kb8], bp0[0], bp0[1]);
            mma_fp16(S[2*ntp0+1], Qf[kb8], bp0[2], bp0[3]);
            mma_fp16(S[2*ntp1],   Qf[kb8], bp1[0], bp1[1]);
            mma_fp16(S[2*ntp1+1], Qf[kb8], bp1[2], bp1[3]);
        }
    };
    // logit chunk ntp: transform S -> l2 (+optional mask), accumulate max
    auto lg_chunk = [&](int ntp, bool diag, int jt) {
        #pragma unroll
        for (int h = 0; h < 2; h++) {
            int nt = 2 * ntp + h;
            float ks0 = h ? ksr_o[2*ntp]     : ksr_e[2*ntp];
            float ks1 = h ? ksr_o[2*ntp + 1] : ksr_e[2*ntp + 1];
            float a0 = fmaf(C2, S[nt][0], -(q2a + ks0));
            float a1 = fmaf(C2, S[nt][1], -(q2a + ks1));
            float c0 = fmaf(C2, S[nt][2], -(q2b + ks0));
            float c1 = fmaf(C2, S[nt][3], -(q2b + ks1));
            if (diag) {
                int cg = jt * BN + nt * 8 + 2 * tig;
                if (cg     > rA) a0 = -3e30f;
                if (cg + 1 > rA) a1 = -3e30f;
                if (cg     > rB) c0 = -3e30f;
                if (cg + 1 > rB) c1 = -3e30f;
            }
            S[nt][0] = a0; S[nt][1] = a1; S[nt][2] = c0; S[nt][3] = c1;
            mxa = fmaxf(mxa, fmaxf(a0, a1));
            mxb = fmaxf(mxb, fmaxf(c0, c1));
        }
    };

    auto tile_body = [&](int jt, bool diag) {
        const uint32_t stg = (uint32_t)(jt & 1) * STAGE_BYTES;
        cp_wait1();
        __syncthreads();

        // ksq -> registers (independent of MMAs; issue early)
        {
            const float* sksq = (const float*)(smc + OFF_KSQ + (jt & 1) * 256);
            #pragma unroll
            for (int q4 = 0; q4 < 4; q4++) {
                float2 ke = *(const float2*)(sksq + q4 * 16 + 2 * tig);
                float2 ko = *(const float2*)(sksq + q4 * 16 + 8 + 2 * tig);
                ksr_e[2*q4] = ke.x; ksr_e[2*q4 + 1] = ke.y;
                ksr_o[2*q4] = ko.x; ksr_o[2*q4 + 1] = ko.y;
            }
        }

        mxa = -3e30f; mxb = -3e30f;
        const uint32_t kbase = smb + stg + k_laneoff;
        // 4-chain pairs; last pair's drain overlaps lg(0),lg(1)
        qk_pair(kbase, 0);
        qk_pair(kbase, 2);
        lg_chunk(0, diag, jt);
        lg_chunk(1, diag, jt);
        lg_chunk(2, diag, jt);
        lg_chunk(3, diag, jt);

        mxa = fmaxf(mxa, __shfl_xor_sync(0xffffffffu, mxa, 1));
        mxa = fmaxf(mxa, __shfl_xor_sync(0xffffffffu, mxa, 2));
        mxb = fmaxf(mxb, __shfl_xor_sync(0xffffffffu, mxb, 1));
        mxb = fmaxf(mxb, __shfl_xor_sync(0xffffffffu, mxb, 2));

        float bna = fmaxf(b_a, mxa - 14.f);
        if (bna > b_a) {
            float f = ex2(b_a - bna);
            #pragma unroll
            for (int dt = 0; dt < 16; dt++) { O[dt][0] *= f; O[dt][1] *= f; }
            b_a = bna;
        }
        float bnb = fmaxf(b_b, mxb - 14.f);
        if (bnb > b_b) {
            float f = ex2(b_b - bnb);
            #pragma unroll
            for (int dt = 0; dt < 16; dt++) { O[dt][2] *= f; O[dt][3] *= f; }
            b_b = bnb;
        }

        // fused exp + PV per 16-col chunk (MUFU overlaps tensor)
        const uint32_t vbase = smb + stg + OFF_V + v_laneoff;
        #pragma unroll
        for (int kj = 0; kj < 4; kj++) {
            uint32_t Pf[4];
            #pragma unroll
            for (int h = 0; h < 2; h++) {
                int nt = kj * 2 + h;
                float p0 = ex2(S[nt][0] - b_a);
                float p1 = ex2(S[nt][1] - b_a);
                float p2 = ex2(S[nt][2] - b_b);
                float p3 = ex2(S[nt][3] - b_b);
                __half2 ha = __floats2half2_rn(p0, p1);
                __half2 hb = __floats2half2_rn(p2, p3);
                Pf[h * 2]     = *(uint32_t*)&ha;
                Pf[h * 2 + 1] = *(uint32_t*)&hb;
            }
            #pragma unroll
            for (int dtp = 0; dtp < 8; dtp++) {
                uint32_t vp[4];
                ldsm_x4_t(vp, vbase + (uint32_t)(kj * 16 * PITCH + dtp * 32));
                mma_fp16(O[2*dtp],   Pf, vp[0], vp[1]);
                mma_fp16(O[2*dtp+1], Pf, vp[2], vp[3]);
            }
        }

        __syncthreads();
        issue_KV(jt + 2);
    };

    for (int jt = 0; jt < iq; jt++) tile_body(jt, false);
    tile_body(iq, true);   // diagonal tile is always last

    // ---- epilogue: descale (O_true = O * 2^b) and store ----
    const float fa = ex2(b_a);
    const float fb = ex2(b_b);
    float* ob = gout + (size_t)bh * NSEQ * DDIM;
    float* oA = ob + (size_t)rA * DDIM;
    float* oB = ob + (size_t)rB * DDIM;
    #pragma unroll
    for (int dt = 0; dt < 16; dt++) {
        int c = dt * 8 + 2 * tig;
        *(float2*)(oA + c) = make_float2(O[dt][0] * fa, O[dt][1] * fa);
        *(float2*)(oB + c) = make_float2(O[dt][2] * fb, O[dt][3] * fb);
    }
}

extern "C" void kernel_launch(void* const* d_in, const int* in_sizes, int n_in,
                              void* d_out, int out_size) {
    const float* q = (const float*)d_in[0];
    const float* k = (const float*)d_in[1];
    const float* v = (const float*)d_in[2];
    float* out = (float*)d_out;

    prepass<<<NROWS / 8, 256>>>(k, v);

    cudaFuncSetAttribute(rbf_attn_hmma,
                         cudaFuncAttributeMaxDynamicSharedMemorySize, SMEM_BYTES);
    dim3 grid(NSEQ / BM, NBH);   // 32 q-tiles x 32 (b,h)
    rbf_attn_hmma<<<grid, 128, SMEM_BYTES>>>(q, out);
}

// round 16
// speedup vs baseline: 1.0360x; 1.0081x over previous
#include <cuda_runtime.h>
#include <cuda_fp16.h>
#include <cstdint>

// =====================================================================
// RBF-kernel causal attention, fp16 HMMA + per-row power-of-2 P scaling.
// Round 16: R13 base with THREE smem stages -> the trailing barrier is
// provably redundant (refill targets buffer (jt-1)%3, freed before this
// tile's leading barrier) => ONE __syncthreads per tile (was 2), cp.async
// slack widens to 2 tiles. 2 CTAs/SM (smem 105.3KB/CTA), reg cap relaxed.
//   l2_ij = log2e*(2s*(q.k) - s||q||^2 - s||k||^2); p = 2^(l2 - b_row);
//   b_row = running max(l2) - 14; O at scale 2^-b, rescaled on growth.
// QK^T and PV both 1-term fp16 (error calibrated rounds 7-13: ~5.4e-4).
// =====================================================================

namespace {
constexpr int NSEQ = 2048;
constexpr int DDIM = 128;
constexpr int BM   = 64;
constexpr int BN   = 64;
constexpr int NBH  = 32;                      // B*H
constexpr int NROWS = NBH * NSEQ;             // 65536
constexpr size_t TOTE = (size_t)NROWS * DDIM; // 8388608
constexpr float SM_SCALE = 0.08838834764831845f;   // 1/sqrt(128)
constexpr float LOG2E    = 1.4426950408889634f;
constexpr float C2       = 2.0f * SM_SCALE * LOG2E;

constexpr int PITCH = 272;   // smem tile row pitch (bytes): 256 data + 16 pad
constexpr uint32_t OFF_V       = 64 * PITCH;            // V offset inside stage
constexpr uint32_t STAGE_BYTES = 2u * 64 * PITCH;       // K + V = 34816
constexpr uint32_t OFF_KSQ     = 3 * STAGE_BYTES;       // 3 x 256B
constexpr uint32_t SMEM_BYTES  = OFF_KSQ + 768 + 128;   // ~105.3 KB per CTA
}

// ---- persistent scratch (alloc-free workaround) ----
__device__ __half g_kh[TOTE];
__device__ __half g_vh[TOTE];
__device__ float  g_ksq[NROWS];   // log2e * s * ||k||^2

__device__ __forceinline__ uint32_t smem_u32(const void* p) {
    uint32_t a;
    asm("{ .reg .u64 t; cvta.to.shared.u64 t, %1; cvt.u32.u64 %0, t; }"
        : "=r"(a) : "l"(p));
    return a;
}
__device__ __forceinline__ void cp16(uint32_t smem_dst, const void* gsrc) {
    asm volatile("cp.async.cg.shared.global [%0], [%1], 16;"
                 :: "r"(smem_dst), "l"(gsrc));
}
__device__ __forceinline__ void cp_commit() {
    asm volatile("cp.async.commit_group;" ::: "memory");
}
__device__ __forceinline__ void cp_wait1() {
    asm volatile("cp.async.wait_group 1;" ::: "memory");
}
__device__ __forceinline__ void ldsm_x4(uint32_t* r, uint32_t addr) {
    asm volatile("ldmatrix.sync.aligned.m8n8.x4.shared.b16 {%0,%1,%2,%3}, [%4];"
                 : "=r"(r[0]), "=r"(r[1]), "=r"(r[2]), "=r"(r[3]) : "r"(addr));
}
__device__ __forceinline__ void ldsm_x4_t(uint32_t* r, uint32_t addr) {
    asm volatile("ldmatrix.sync.aligned.m8n8.x4.trans.shared.b16 {%0,%1,%2,%3}, [%4];"
                 : "=r"(r[0]), "=r"(r[1]), "=r"(r[2]), "=r"(r[3]) : "r"(addr));
}
__device__ __forceinline__ void mma_fp16(float* d, const uint32_t* a,
                                         uint32_t b0, uint32_t b1) {
    asm volatile(
        "mma.sync.aligned.m16n8k16.row.col.f32.f16.f16.f32 "
        "{%0,%1,%2,%3}, {%4,%5,%6,%7}, {%8,%9}, {%0,%1,%2,%3};"
        : "+f"(d[0]), "+f"(d[1]), "+f"(d[2]), "+f"(d[3])
        : "r"(a[0]), "r"(a[1]), "r"(a[2]), "r"(a[3]), "r"(b0), "r"(b1));
}
__device__ __forceinline__ float ex2(float x) {
    float y;
    asm("ex2.approx.ftz.f32 %0, %1;" : "=f"(y) : "f"(x));
    return y;
}

// =========================== pre-pass (K, V only) ===========================
__global__ __launch_bounds__(256)
void prepass(const float* __restrict__ gk,
             const float* __restrict__ gv) {
    const int warp = threadIdx.x >> 5;
    const int lane = threadIdx.x & 31;
    const int row  = blockIdx.x * 8 + warp;
    const size_t e = (size_t)row * DDIM + lane * 4;

    float4 kx = *(const float4*)(gk + e);
    {
        __half2 a = __floats2half2_rn(kx.x, kx.y);
        __half2 b = __floats2half2_rn(kx.z, kx.w);
        *(uint2*)&g_kh[e] = make_uint2(*(uint32_t*)&a, *(uint32_t*)&b);
    }
    float s2 = kx.x*kx.x + kx.y*kx.y + kx.z*kx.z + kx.w*kx.w;
    #pragma unroll
    for (int o = 16; o; o >>= 1) s2 += __shfl_xor_sync(0xffffffffu, s2, o);
    if (lane == 0) g_ksq[row] = (SM_SCALE * LOG2E) * s2;

    float4 vx = *(const float4*)(gv + e);
    {
        __half2 a = __floats2half2_rn(vx.x, vx.y);
        __half2 b = __floats2half2_rn(vx.z, vx.w);
        *(uint2*)&g_vh[e] = make_uint2(*(uint32_t*)&a, *(uint32_t*)&b);
    }
}

// =========================== main kernel ===========================
__global__ __launch_bounds__(128, 2)
void rbf_attn_hmma(const float* __restrict__ gq, float* __restrict__ gout) {
    extern __shared__ char smc[];
    const uint32_t smb = smem_u32(smc);
    const int tid  = threadIdx.x;
    const int warp = tid >> 5;        // 0..3
    const int lane = tid & 31;
    const int g    = lane >> 2;
    const int tig  = lane & 3;
    const int iq   = (int)gridDim.x - 1 - (int)blockIdx.x;   // big tiles first
    const int bh   = blockIdx.y;

    const size_t rowbase = (size_t)bh * NSEQ;
    const int njt = iq + 1;

    // ---- stage loader: K + V + ksq of tile jt, one commit group ----
    auto issue_KV = [&](int jt) {
        if (jt < njt) {
            const uint32_t stg = (uint32_t)(jt % 3) * STAGE_BYTES;
            const size_t eb = (rowbase + (size_t)jt * BN) * DDIM;
            #pragma unroll
            for (int i = 0; i < 8; i++) {
                int c = i * 128 + tid;           // 0..1023
                int r = c >> 4, col = c & 15;
                uint32_t d = (uint32_t)(r * PITCH + col * 16);
                const size_t gsrc = eb + r * DDIM + col * 8;
                cp16(smb + stg + d,         g_kh + gsrc);
                cp16(smb + stg + OFF_V + d, g_vh + gsrc);
            }
            if (tid < 16)
                cp16(smb + OFF_KSQ + (uint32_t)((jt % 3) * 256 + tid * 16),
                     g_ksq + rowbase + jt * BN + tid * 4);
        }
        cp_commit();
    };

    issue_KV(0);
    issue_KV(1);

    // ---- prologue: Q fp32 -> fp16 fragments + log2-scaled row norms ----
    const int rowA = warp * 16 + g;           // 0..63
    const int rA   = iq * BM + rowA;          // row within head
    const int rB   = rA + 8;
    const float* qA = gq + (rowbase + rA) * (size_t)DDIM;
    const float* qB = qA + 8 * DDIM;
    uint32_t Qf[8][4];
    float q2a = 0.f, q2b = 0.f;
    #pragma unroll
    for (int kb8 = 0; kb8 < 8; kb8++) {
        int c0 = kb8 * 16 + 2 * tig;
        float2 a0 = *(const float2*)(qA + c0);
        float2 a1 = *(const float2*)(qA + c0 + 8);
        float2 b0 = *(const float2*)(qB + c0);
        float2 b1 = *(const float2*)(qB + c0 + 8);
        q2a += a0.x*a0.x + a0.y*a0.y + a1.x*a1.x + a1.y*a1.y;
        q2b += b0.x*b0.x + b0.y*b0.y + b1.x*b1.x + b1.y*b1.y;
        __half2 ha0 = __floats2half2_rn(a0.x, a0.y);
        __half2 hb0 = __floats2half2_rn(b0.x, b0.y);
        __half2 ha1 = __floats2half2_rn(a1.x, a1.y);
        __half2 hb1 = __floats2half2_rn(b1.x, b1.y);
        Qf[kb8][0] = *(uint32_t*)&ha0;
        Qf[kb8][1] = *(uint32_t*)&hb0;
        Qf[kb8][2] = *(uint32_t*)&ha1;
        Qf[kb8][3] = *(uint32_t*)&hb1;
    }
    q2a += __shfl_xor_sync(0xffffffffu, q2a, 1);
    q2a += __shfl_xor_sync(0xffffffffu, q2a, 2);
    q2b += __shfl_xor_sync(0xffffffffu, q2b, 1);
    q2b += __shfl_xor_sync(0xffffffffu, q2b, 2);
    q2a *= SM_SCALE * LOG2E;
    q2b *= SM_SCALE * LOG2E;

    float O[16][4];
    #pragma unroll
    for (int i = 0; i < 16; i++)
        #pragma unroll
        for (int j = 0; j < 4; j++) O[i][j] = 0.f;
    float b_a = -3e30f, b_b = -3e30f;   // running log2-bias per row half

    const uint32_t k_laneoff = (uint32_t)(((lane & 7) + ((lane & 16) >> 1)) * PITCH
                                          + (lane & 8) * 2);
    const uint32_t v_laneoff = (uint32_t)(((lane & 7) + (lane & 8)) * PITCH
                                          + (lane & 16));

    float S[8][4];
    float ksr_e[8], ksr_o[8];
    float mxa, mxb;

    // qk chunk ntp: 8 ldsm + 16 MMAs finishing S[2ntp], S[2ntp+1]
    auto qk_chunk = [&](uint32_t kbase, int ntp) {
        S[2*ntp][0] = 0.f; S[2*ntp][1] = 0.f; S[2*ntp][2] = 0.f; S[2*ntp][3] = 0.f;
        S[2*ntp+1][0] = 0.f; S[2*ntp+1][1] = 0.f; S[2*ntp+1][2] = 0.f; S[2*ntp+1][3] = 0.f;
        #pragma unroll
        for (int kb8 = 0; kb8 < 8; kb8++) {
            uint32_t bp[4];
            ldsm_x4(bp, kbase + (uint32_t)(ntp * 16 * PITCH + kb8 * 32));
            mma_fp16(S[2*ntp],   Qf[kb8], bp[0], bp[1]);
            mma_fp16(S[2*ntp+1], Qf[kb8], bp[2], bp[3]);
        }
    };
    // logit chunk ntp: transform S -> l2 (+optional mask), accumulate max
    auto lg_chunk = [&](int ntp, bool diag, int jt) {
        #pragma unroll
        for (int h = 0; h < 2; h++) {
            int nt = 2 * ntp + h;
            float ks0 = h ? ksr_o[2*ntp]     : ksr_e[2*ntp];
            float ks1 = h ? ksr_o[2*ntp + 1] : ksr_e[2*ntp + 1];
            float a0 = fmaf(C2, S[nt][0], -(q2a + ks0));
            float a1 = fmaf(C2, S[nt][1], -(q2a + ks1));
            float c0 = fmaf(C2, S[nt][2], -(q2b + ks0));
            float c1 = fmaf(C2, S[nt][3], -(q2b + ks1));
            if (diag) {
                int cg = jt * BN + nt * 8 + 2 * tig;
                if (cg     > rA) a0 = -3e30f;
                if (cg + 1 > rA) a1 = -3e30f;
                if (cg     > rB) c0 = -3e30f;
                if (cg + 1 > rB) c1 = -3e30f;
            }
            S[nt][0] = a0; S[nt][1] = a1; S[nt][2] = c0; S[nt][3] = c1;
            mxa = fmaxf(mxa, fmaxf(a0, a1));
            mxb = fmaxf(mxb, fmaxf(c0, c1));
        }
    };

    auto tile_body = [&](int jt, bool diag) {
        const uint32_t stg = (uint32_t)(jt % 3) * STAGE_BYTES;
        cp_wait1();          // tile jt resident (jt+1 still in flight)
        __syncthreads();     // ONLY barrier: also certifies tile jt-1 fully read
        issue_KV(jt + 2);    // refills buffer (jt-1)%3 — free by the line above

        // ksq -> registers (independent of MMAs; issue early)
        {
            const float* sksq = (const float*)(smc + OFF_KSQ + (jt % 3) * 256);
            #pragma unroll
            for (int q4 = 0; q4 < 4; q4++) {
                float2 ke = *(const float2*)(sksq + q4 * 16 + 2 * tig);
                float2 ko = *(const float2*)(sksq + q4 * 16 + 8 + 2 * tig);
                ksr_e[2*q4] = ke.x; ksr_e[2*q4 + 1] = ke.y;
                ksr_o[2*q4] = ko.x; ksr_o[2*q4 + 1] = ko.y;
            }
        }

        mxa = -3e30f; mxb = -3e30f;
        const uint32_t kbase = smb + stg + k_laneoff;
        // pipeline: logit ALU of chunk c overlaps MMA drain of chunk c+1
        qk_chunk(kbase, 0);
        qk_chunk(kbase, 1);
        lg_chunk(0, diag, jt);
        qk_chunk(kbase, 2);
        lg_chunk(1, diag, jt);
        qk_chunk(kbase, 3);
        lg_chunk(2, diag, jt);
        lg_chunk(3, diag, jt);

        mxa = fmaxf(mxa, __shfl_xor_sync(0xffffffffu, mxa, 1));
        mxa = fmaxf(mxa, __shfl_xor_sync(0xffffffffu, mxa, 2));
        mxb = fmaxf(mxb, __shfl_xor_sync(0xffffffffu, mxb, 1));
        mxb = fmaxf(mxb, __shfl_xor_sync(0xffffffffu, mxb, 2));

        float bna = fmaxf(b_a, mxa - 14.f);
        if (bna > b_a) {
            float f = ex2(b_a - bna);
            #pragma unroll
            for (int dt = 0; dt < 16; dt++) { O[dt][0] *= f; O[dt][1] *= f; }
            b_a = bna;
        }
        float bnb = fmaxf(b_b, mxb - 14.f);
        if (bnb > b_b) {
            float f = ex2(b_b - bnb);
            #pragma unroll
            for (int dt = 0; dt < 16; dt++) { O[dt][2] *= f; O[dt][3] *= f; }
            b_b = bnb;
        }

        // fused exp + PV per 16-col chunk (MUFU overlaps tensor)
        const uint32_t vbase = smb + stg + OFF_V + v_laneoff;
        #pragma unroll
        for (int kj = 0; kj < 4; kj++) {
            uint32_t Pf[4];
            #pragma unroll
            for (int h = 0; h < 2; h++) {
                int nt = kj * 2 + h;
                float p0 = ex2(S[nt][0] - b_a);
                float p1 = ex2(S[nt][1] - b_a);
                float p2 = ex2(S[nt][2] - b_b);
                float p3 = ex2(S[nt][3] - b_b);
                __half2 ha = __floats2half2_rn(p0, p1);
                __half2 hb = __floats2half2_rn(p2, p3);
                Pf[h * 2]     = *(uint32_t*)&ha;
                Pf[h * 2 + 1] = *(uint32_t*)&hb;
            }
            #pragma unroll
            for (int dtp = 0; dtp < 8; dtp++) {
                uint32_t vp[4];
                ldsm_x4_t(vp, vbase + (uint32_t)(kj * 16 * PITCH + dtp * 32));
                mma_fp16(O[2*dtp],   Pf, vp[0], vp[1]);
                mma_fp16(O[2*dtp+1], Pf, vp[2], vp[3]);
            }
        }
    };

    for (int jt = 0; jt < iq; jt++) tile_body(jt, false);
    tile_body(iq, true);   // diagonal tile is always last

    // ---- epilogue: descale (O_true = O * 2^b) and store ----
    const float fa = ex2(b_a);
    const float fb = ex2(b_b);
    float* ob = gout + (size_t)bh * NSEQ * DDIM;
    float* oA = ob + (size_t)rA * DDIM;
    float* oB = ob + (size_t)rB * DDIM;
    #pragma unroll
    for (int dt = 0; dt < 16; dt++) {
        int c = dt * 8 + 2 * tig;
        *(float2*)(oA + c) = make_float2(O[dt][0] * fa, O[dt][1] * fa);
        *(float2*)(oB + c) = make_float2(O[dt][2] * fb, O[dt][3] * fb);
    }
}

extern "C" void kernel_launch(void* const* d_in, const int* in_sizes, int n_in,
                              void* d_out, int out_size) {
    const float* q = (const float*)d_in[0];
    const float* k = (const float*)d_in[1];
    const float* v = (const float*)d_in[2];
    float* out = (float*)d_out;

    prepass<<<NROWS / 8, 256>>>(k, v);

    cudaFuncSetAttribute(rbf_attn_hmma,
                         cudaFuncAttributeMaxDynamicSharedMemorySize, SMEM_BYTES);
    dim3 grid(NSEQ / BM, NBH);   // 32 q-tiles x 32 (b,h)
    rbf_attn_hmma<<<grid, 128, SMEM_BYTES>>>(q, out);
}

// round 17
// speedup vs baseline: 1.0537x; 1.0170x over previous
#include <cuda_runtime.h>
#include <cuda_fp16.h>
#include <cstdint>

// =====================================================================
// RBF-kernel causal attention, fp16 HMMA + lazy power-of-2 P scaling.
// Round 17: R13 base + LAZY BIAS — logits computed directly in the biased
// domain (b folded into per-row constant q2ab); the cross-thread shuffle-max,
// bias update and O-rescale run ONLY when a warp vote detects a tile whose
// biased max exceeds +15 (fp16 overflow risk) — ~10-15% of tiles. Saves two
// dependent SHFL chains + 32 subs on every other tile.
//   l2b_ij = log2e*(2s*(q.k) - s||q||^2 - s||k||^2) - b_row; p = 2^(l2b);
//   valid while l2b <= 16 (fp16 top) ; dominant elements keep >=2^-11 rel.
// QK^T and PV both 1-term fp16 (error calibrated rounds 7-13: ~5.4e-4).
// 3 CTAs/SM, 2-stage cp.async, diag-split, QK/logit interleave.
// =====================================================================

namespace {
constexpr int NSEQ = 2048;
constexpr int DDIM = 128;
constexpr int BM   = 64;
constexpr int BN   = 64;
constexpr int NBH  = 32;                      // B*H
constexpr int NROWS = NBH * NSEQ;             // 65536
constexpr size_t TOTE = (size_t)NROWS * DDIM; // 8388608
constexpr float SM_SCALE = 0.08838834764831845f;   // 1/sqrt(128)
constexpr float LOG2E    = 1.4426950408889634f;
constexpr float C2       = 2.0f * SM_SCALE * LOG2E;

constexpr int PITCH = 272;   // smem tile row pitch (bytes): 256 data + 16 pad
constexpr uint32_t OFF_V       = 64 * PITCH;            // V offset inside stage
constexpr uint32_t STAGE_BYTES = 2u * 64 * PITCH;       // K + V = 34816
constexpr uint32_t OFF_KSQ     = 2 * STAGE_BYTES;       // 2 x 256B
constexpr uint32_t SMEM_BYTES  = OFF_KSQ + 512 + 128;   // 70272 per CTA
}

// ---- persistent scratch (alloc-free workaround) ----
__device__ __half g_kh[TOTE];
__device__ __half g_vh[TOTE];
__device__ float  g_ksq[NROWS];   // log2e * s * ||k||^2

__device__ __forceinline__ uint32_t smem_u32(const void* p) {
    uint32_t a;
    asm("{ .reg .u64 t; cvta.to.shared.u64 t, %1; cvt.u32.u64 %0, t; }"
        : "=r"(a) : "l"(p));
    return a;
}
__device__ __forceinline__ void cp16(uint32_t smem_dst, const void* gsrc) {
    asm volatile("cp.async.cg.shared.global [%0], [%1], 16;"
                 :: "r"(smem_dst), "l"(gsrc));
}
__device__ __forceinline__ void cp_commit() {
    asm volatile("cp.async.commit_group;" ::: "memory");
}
__device__ __forceinline__ void cp_wait1() {
    asm volatile("cp.async.wait_group 1;" ::: "memory");
}
__device__ __forceinline__ void ldsm_x4(uint32_t* r, uint32_t addr) {
    asm volatile("ldmatrix.sync.aligned.m8n8.x4.shared.b16 {%0,%1,%2,%3}, [%4];"
                 : "=r"(r[0]), "=r"(r[1]), "=r"(r[2]), "=r"(r[3]) : "r"(addr));
}
__device__ __forceinline__ void ldsm_x4_t(uint32_t* r, uint32_t addr) {
    asm volatile("ldmatrix.sync.aligned.m8n8.x4.trans.shared.b16 {%0,%1,%2,%3}, [%4];"
                 : "=r"(r[0]), "=r"(r[1]), "=r"(r[2]), "=r"(r[3]) : "r"(addr));
}
__device__ __forceinline__ void mma_fp16(float* d, const uint32_t* a,
                                         uint32_t b0, uint32_t b1) {
    asm volatile(
        "mma.sync.aligned.m16n8k16.row.col.f32.f16.f16.f32 "
        "{%0,%1,%2,%3}, {%4,%5,%6,%7}, {%8,%9}, {%0,%1,%2,%3};"
        : "+f"(d[0]), "+f"(d[1]), "+f"(d[2]), "+f"(d[3])
        : "r"(a[0]), "r"(a[1]), "r"(a[2]), "r"(a[3]), "r"(b0), "r"(b1));
}
__device__ __forceinline__ float ex2(float x) {
    float y;
    asm("ex2.approx.ftz.f32 %0, %1;" : "=f"(y) : "f"(x));
    return y;
}

// =========================== pre-pass (K, V only) ===========================
__global__ __launch_bounds__(256)
void prepass(const float* __restrict__ gk,
             const float* __restrict__ gv) {
    const int warp = threadIdx.x >> 5;
    const int lane = threadIdx.x & 31;
    const int row  = blockIdx.x * 8 + warp;
    const size_t e = (size_t)row * DDIM + lane * 4;

    float4 kx = *(const float4*)(gk + e);
    {
        __half2 a = __floats2half2_rn(kx.x, kx.y);
        __half2 b = __floats2half2_rn(kx.z, kx.w);
        *(uint2*)&g_kh[e] = make_uint2(*(uint32_t*)&a, *(uint32_t*)&b);
    }
    float s2 = kx.x*kx.x + kx.y*kx.y + kx.z*kx.z + kx.w*kx.w;
    #pragma unroll
    for (int o = 16; o; o >>= 1) s2 += __shfl_xor_sync(0xffffffffu, s2, o);
    if (lane == 0) g_ksq[row] = (SM_SCALE * LOG2E) * s2;

    float4 vx = *(const float4*)(gv + e);
    {
        __half2 a = __floats2half2_rn(vx.x, vx.y);
        __half2 b = __floats2half2_rn(vx.z, vx.w);
        *(uint2*)&g_vh[e] = make_uint2(*(uint32_t*)&a, *(uint32_t*)&b);
    }
}

// =========================== main kernel ===========================
__global__ __launch_bounds__(128, 3)
void rbf_attn_hmma(const float* __restrict__ gq, float* __restrict__ gout) {
    extern __shared__ char smc[];
    const uint32_t smb = smem_u32(smc);
    const int tid  = threadIdx.x;
    const int warp = tid >> 5;        // 0..3
    const int lane = tid & 31;
    const int g    = lane >> 2;
    const int tig  = lane & 3;
    const int iq   = (int)gridDim.x - 1 - (int)blockIdx.x;   // big tiles first
    const int bh   = blockIdx.y;

    const size_t rowbase = (size_t)bh * NSEQ;
    const int njt = iq + 1;

    // ---- stage loader: K + V + ksq of tile jt, one commit group ----
    auto issue_KV = [&](int jt) {
        if (jt < njt) {
            const uint32_t stg = (uint32_t)(jt & 1) * STAGE_BYTES;
            const size_t eb = (rowbase + (size_t)jt * BN) * DDIM;
            #pragma unroll
            for (int i = 0; i < 8; i++) {
                int c = i * 128 + tid;           // 0..1023
                int r = c >> 4, col = c & 15;
                uint32_t d = (uint32_t)(r * PITCH + col * 16);
                const size_t gsrc = eb + r * DDIM + col * 8;
                cp16(smb + stg + d,         g_kh + gsrc);
                cp16(smb + stg + OFF_V + d, g_vh + gsrc);
            }
            if (tid < 16)
                cp16(smb + OFF_KSQ + (uint32_t)((jt & 1) * 256 + tid * 16),
                     g_ksq + rowbase + jt * BN + tid * 4);
        }
        cp_commit();
    };

    issue_KV(0);
    issue_KV(1);

    // ---- prologue: Q fp32 -> fp16 fragments + log2-scaled row norms ----
    const int rowA = warp * 16 + g;           // 0..63
    const int rA   = iq * BM + rowA;          // row within head
    const int rB   = rA + 8;
    const float* qA = gq + (rowbase + rA) * (size_t)DDIM;
    const float* qB = qA + 8 * DDIM;
    uint32_t Qf[8][4];
    float q2a = 0.f, q2b = 0.f;
    #pragma unroll
    for (int kb8 = 0; kb8 < 8; kb8++) {
        int c0 = kb8 * 16 + 2 * tig;
        float2 a0 = *(const float2*)(qA + c0);
        float2 a1 = *(const float2*)(qA + c0 + 8);
        float2 b0 = *(const float2*)(qB + c0);
        float2 b1 = *(const float2*)(qB + c0 + 8);
        q2a += a0.x*a0.x + a0.y*a0.y + a1.x*a1.x + a1.y*a1.y;
        q2b += b0.x*b0.x + b0.y*b0.y + b1.x*b1.x + b1.y*b1.y;
        __half2 ha0 = __floats2half2_rn(a0.x, a0.y);
        __half2 hb0 = __floats2half2_rn(b0.x, b0.y);
        __half2 ha1 = __floats2half2_rn(a1.x, a1.y);
        __half2 hb1 = __floats2half2_rn(b1.x, b1.y);
        Qf[kb8][0] = *(uint32_t*)&ha0;
        Qf[kb8][1] = *(uint32_t*)&hb0;
        Qf[kb8][2] = *(uint32_t*)&ha1;
        Qf[kb8][3] = *(uint32_t*)&hb1;
    }
    q2a += __shfl_xor_sync(0xffffffffu, q2a, 1);
    q2a += __shfl_xor_sync(0xffffffffu, q2a, 2);
    q2b += __shfl_xor_sync(0xffffffffu, q2b, 1);
    q2b += __shfl_xor_sync(0xffffffffu, q2b, 2);
    q2a *= SM_SCALE * LOG2E;
    q2b *= SM_SCALE * LOG2E;

    float O[16][4];
    #pragma unroll
    for (int i = 0; i < 16; i++)
        #pragma unroll
        for (int j = 0; j < 4; j++) O[i][j] = 0.f;

    // lazy bias: b starts at -1000 sentinel -> first tile's biased logits
    // ~ +970 > 15 forces an update (fp32 keeps ~1e-4 abs precision there).
    float b_a = -1000.f, b_b = -1000.f;
    float q2ab_a = q2a + b_a;     // folded constant: l2b = C2*S - (q2ab + ks)
    float q2ab_b = q2b + b_b;

    const uint32_t k_laneoff = (uint32_t)(((lane & 7) + ((lane & 16) >> 1)) * PITCH
                                          + (lane & 8) * 2);
    const uint32_t v_laneoff = (uint32_t)(((lane & 7) + (lane & 8)) * PITCH
                                          + (lane & 16));

    float S[8][4];
    float ksr_e[8], ksr_o[8];
    float mxa, mxb;

    // qk chunk ntp: 8 ldsm + 16 MMAs finishing S[2ntp], S[2ntp+1]
    auto qk_chunk = [&](uint32_t kbase, int ntp) {
        S[2*ntp][0] = 0.f; S[2*ntp][1] = 0.f; S[2*ntp][2] = 0.f; S[2*ntp][3] = 0.f;
        S[2*ntp+1][0] = 0.f; S[2*ntp+1][1] = 0.f; S[2*ntp+1][2] = 0.f; S[2*ntp+1][3] = 0.f;
        #pragma unroll
        for (int kb8 = 0; kb8 < 8; kb8++) {
            uint32_t bp[4];
            ldsm_x4(bp, kbase + (uint32_t)(ntp * 16 * PITCH + kb8 * 32));
            mma_fp16(S[2*ntp],   Qf[kb8], bp[0], bp[1]);
            mma_fp16(S[2*ntp+1], Qf[kb8], bp[2], bp[3]);
        }
    };
    // logit chunk ntp: S -> BIASED log2-logits (+mask), per-thread max
    auto lg_chunk = [&](int ntp, bool diag, int jt) {
        #pragma unroll
        for (int h = 0; h < 2; h++) {
            int nt = 2 * ntp + h;
            float ks0 = h ? ksr_o[2*ntp]     : ksr_e[2*ntp];
            float ks1 = h ? ksr_o[2*ntp + 1] : ksr_e[2*ntp + 1];
            float a0 = fmaf(C2, S[nt][0], -(q2ab_a + ks0));
            float a1 = fmaf(C2, S[nt][1], -(q2ab_a + ks1));
            float c0 = fmaf(C2, S[nt][2], -(q2ab_b + ks0));
            float c1 = fmaf(C2, S[nt][3], -(q2ab_b + ks1));
            if (diag) {
                int cg = jt * BN + nt * 8 + 2 * tig;
                if (cg     > rA) a0 = -3e30f;
                if (cg + 1 > rA) a1 = -3e30f;
                if (cg     > rB) c0 = -3e30f;
                if (cg + 1 > rB) c1 = -3e30f;
            }
            S[nt][0] = a0; S[nt][1] = a1; S[nt][2] = c0; S[nt][3] = c1;
            mxa = fmaxf(mxa, fmaxf(a0, a1));
            mxb = fmaxf(mxb, fmaxf(c0, c1));
        }
    };

    auto tile_body = [&](int jt, bool diag) {
        const uint32_t stg = (uint32_t)(jt & 1) * STAGE_BYTES;
        cp_wait1();
        __syncthreads();

        // ksq -> registers (independent of MMAs; issue early)
        {
            const float* sksq = (const float*)(smc + OFF_KSQ + (jt & 1) * 256);
            #pragma unroll
            for (int q4 = 0; q4 < 4; q4++) {
                float2 ke = *(const float2*)(sksq + q4 * 16 + 2 * tig);
                float2 ko = *(const float2*)(sksq + q4 * 16 + 8 + 2 * tig);
                ksr_e[2*q4] = ke.x; ksr_e[2*q4 + 1] = ke.y;
                ksr_o[2*q4] = ko.x; ksr_o[2*q4 + 1] = ko.y;
            }
        }

        mxa = -3e30f; mxb = -3e30f;
        const uint32_t kbase = smb + stg + k_laneoff;
        // pipeline: logit ALU of chunk c overlaps MMA drain of chunk c+1
        qk_chunk(kbase, 0);
        qk_chunk(kbase, 1);
        lg_chunk(0, diag, jt);
        qk_chunk(kbase, 2);
        lg_chunk(1, diag, jt);
        qk_chunk(kbase, 3);
        lg_chunk(2, diag, jt);
        lg_chunk(3, diag, jt);

        // ---- lazy bias: update only if a row risks fp16 overflow ----
        if (__any_sync(0xffffffffu, (mxa > 15.f) | (mxb > 15.f))) {
            mxa = fmaxf(mxa, __shfl_xor_sync(0xffffffffu, mxa, 1));
            mxa = fmaxf(mxa, __shfl_xor_sync(0xffffffffu, mxa, 2));
            mxb = fmaxf(mxb, __shfl_xor_sync(0xffffffffu, mxb, 1));
            mxb = fmaxf(mxb, __shfl_xor_sync(0xffffffffu, mxb, 2));
            float da = fmaxf(mxa - 14.f, 0.f);
            float db = fmaxf(mxb - 14.f, 0.f);
            float fa_ = ex2(-da), fb_ = ex2(-db);
            #pragma unroll
            for (int dt = 0; dt < 16; dt++) {
                O[dt][0] *= fa_; O[dt][1] *= fa_;
                O[dt][2] *= fb_; O[dt][3] *= fb_;
            }
            #pragma unroll
            for (int nt = 0; nt < 8; nt++) {
                S[nt][0] -= da; S[nt][1] -= da;
                S[nt][2] -= db; S[nt][3] -= db;
            }
            b_a += da;  q2ab_a += da;
            b_b += db;  q2ab_b += db;
        }

        // fused exp + PV per 16-col chunk (MUFU overlaps tensor);
        // S already holds BIASED logits -> p = 2^S directly
        const uint32_t vbase = smb + stg + OFF_V + v_laneoff;
        #pragma unroll
        for (int kj = 0; kj < 4; kj++) {
            uint32_t Pf[4];
            #pragma unroll
            for (int h = 0; h < 2; h++) {
                int nt = kj * 2 + h;
                float p0 = ex2(S[nt][0]);
                float p1 = ex2(S[nt][1]);
                float p2 = ex2(S[nt][2]);
                float p3 = ex2(S[nt][3]);
                __half2 ha = __floats2half2_rn(p0, p1);
                __half2 hb = __floats2half2_rn(p2, p3);
                Pf[h * 2]     = *(uint32_t*)&ha;
                Pf[h * 2 + 1] = *(uint32_t*)&hb;
            }
            #pragma unroll
            for (int dtp = 0; dtp < 8; dtp++) {
                uint32_t vp[4];
                ldsm_x4_t(vp, vbase + (uint32_t)(kj * 16 * PITCH + dtp * 32));
                mma_fp16(O[2*dtp],   Pf, vp[0], vp[1]);
                mma_fp16(O[2*dtp+1], Pf, vp[2], vp[3]);
            }
        }

        __syncthreads();
        issue_KV(jt + 2);
    };

    for (int jt = 0; jt < iq; jt++) tile_body(jt, false);
    tile_body(iq, true);   // diagonal tile is always last

    // ---- epilogue: descale (O_true = O * 2^b) and store ----
    const float fa = ex2(b_a);
    const float fb = ex2(b_b);
    float* ob = gout + (size_t)bh * NSEQ * DDIM;
    float* oA = ob + (size_t)rA * DDIM;
    float* oB = ob + (size_t)rB * DDIM;
    #pragma unroll
    for (int dt = 0; dt < 16; dt++) {
        int c = dt * 8 + 2 * tig;
        *(float2*)(oA + c) = make_float2(O[dt][0] * fa, O[dt][1] * fa);
        *(float2*)(oB + c) = make_float2(O[dt][2] * fb, O[dt][3] * fb);
    }
}

extern "C" void kernel_launch(void* const* d_in, const int* in_sizes, int n_in,
                              void* d_out, int out_size) {
    const float* q = (const float*)d_in[0];
    const float* k = (const float*)d_in[1];
    const float* v = (const float*)d_in[2];
    float* out = (float*)d_out;

    prepass<<<NROWS / 8, 256>>>(k, v);

    cudaFuncSetAttribute(rbf_attn_hmma,
                         cudaFuncAttributeMaxDynamicSharedMemorySize, SMEM_BYTES);
    dim3 grid(NSEQ / BM, NBH);   // 32 q-tiles x 32 (b,h)
    rbf_attn_hmma<<<grid, 128, SMEM_BYTES>>>(q, out);
}